// round 7
// baseline (speedup 1.0000x reference)
#include <cuda_runtime.h>
#include <cuda_fp16.h>
#include <cfloat>
#include <cstdint>

#define BB 8
#define CC 3
#define HH 1080
#define WW 1920
#define KK 256
#define NBASIS 25
#define GBINS 8192          // power of two: x*8192.0f and frac are EXACT in fp32
#define NSEG (KK + 1)       // 257 extended segments
#define PIX_PER_BATCH (CC * HH * WW)   // 6,220,800
#define NF4 (PIX_PER_BATCH / 4)        // 1,555,200
#define GX 111                          // blocks per batch: 111*8 = 888 = 148*6
#define STRIDE (GX * 256)               // 28,416
// 54 full strides cover 54*28416 = 1,534,464 ; remainder 20,736
#define PAIRS 27

// Bin entry (uint32):
//   pure bin -> lo16 = half(y_left), hi16 = half(y_right)
//   kinked   -> lo16 = fp16 NaN with payload: 0x7C00 | (k0+1)   (k0 <= 256)
__device__ uint32_t gBinsU[BB * GBINS];
__device__ float    gSegHi[BB * NSEG];   // segment upper bound E[k] (FLT_MAX for k=K)
__device__ float2   gSegAB[BB * NSEG];   // exact (slope, intercept)

// ---------------------------------------------------------------------------
// Table builder: grid (BB, 33), 256 threads.
//   blockIdx.y in [0,32): build 256 bins each;  ==32: build segment table.
// ---------------------------------------------------------------------------
__global__ void tmo_tables(const float* __restrict__ w,
                           const float* __restrict__ E,
                           const float* __restrict__ f0,
                           const float* __restrict__ Hb) {
    __shared__ float sE[KK];
    __shared__ float sC[KK];
    const int b = blockIdx.x;
    const int part = blockIdx.y;
    const int t = threadIdx.x;

    {
        float acc = f0[t];
        #pragma unroll
        for (int n = 0; n < NBASIS; n++)
            acc = fmaf(Hb[t * NBASIS + n], w[b * NBASIS + n], acc);
        sE[t] = E[t];
        sC[t] = acc;
    }
    __syncthreads();

    if (part == 32) {
        for (int k = t; k < NSEG; k += blockDim.x) {
            float hi; float2 ab;
            if (k == 0) {
                hi = sE[0];            ab = make_float2(0.0f, sC[0]);
            } else if (k == KK) {
                hi = FLT_MAX;          ab = make_float2(0.0f, sC[KK - 1]);
            } else {
                float a = (sC[k] - sC[k - 1]) / (sE[k] - sE[k - 1]);
                hi = sE[k];            ab = make_float2(a, fmaf(-a, sE[k - 1], sC[k - 1]));
            }
            gSegHi[b * NSEG + k] = hi;
            gSegAB[b * NSEG + k] = ab;
        }
    } else {
        const int g = part * 256 + t;
        float left  = (float)g       * (1.0f / GBINS);  // exact
        float right = (float)(g + 1) * (1.0f / GBINS);  // exact
        int lo = 0, hi = KK;
        while (lo < hi) {                // k0 = #E <= left
            int mid = (lo + hi) >> 1;
            if (sE[mid] <= left) lo = mid + 1; else hi = mid;
        }
        int k0 = lo;
        float upper = (k0 < KK) ? sE[k0] : FLT_MAX;
        uint32_t u;
        if (upper >= right) {
            float yl, yr;
            if (k0 == 0) {
                yl = yr = sC[0];
            } else if (k0 == KK) {
                yl = yr = sC[KK - 1];
            } else {
                float a = (sC[k0] - sC[k0 - 1]) / (sE[k0] - sE[k0 - 1]);
                float bint = fmaf(-a, sE[k0 - 1], sC[k0 - 1]);
                yl = fmaf(a, left,  bint);
                yr = fmaf(a, right, bint);
            }
            uint16_t hl = __half_as_ushort(__float2half_rn(yl));
            uint16_t hr = __half_as_ushort(__float2half_rn(yr));
            u = ((uint32_t)hr << 16) | hl;          // finite halfs: never NaN-pattern
        } else {
            u = 0x7C000000u | (0x7C00u | (uint32_t)(k0 + 1));  // NaN sentinel + payload
        }
        gBinsU[b * GBINS + g] = u;
    }
}

// ---------------------------------------------------------------------------
// Main kernel: grid (111, 8) = 888 blocks = one wave at 6 CTAs/SM.
// ~36 KB shared. Fast path: LDS.32 + lerp (branchless); slow path triggered
// by NaN result (~3% of lanes): exact fp32 segment walk in shared.
// Unroll x2: two independent LDG.128 in flight per iteration.
// ---------------------------------------------------------------------------
__device__ __forceinline__ float tmo_eval(float x, const uint32_t* sBins,
                                          const float* sHi, const float2* sAB) {
    float xg = x * (float)GBINS;           // exact
    int g = (int)xg;                        // x in [0,1) -> g in [0, GBINS-1]
    uint32_t u = sBins[g];
    float2 yy = __half22float2(*reinterpret_cast<const __half2*>(&u));
    float frac = xg - (float)g;            // exact
    float y = fmaf(yy.y - yy.x, frac, yy.x);
    if (!(y == y)) {                        // NaN => kinked bin
        int k = (int)(u & 0x3FFu) - 1;
        while (x >= sHi[k]) k++;
        float2 ab = sAB[k];
        y = fmaf(ab.x, x, ab.y);
    }
    return __saturatef(y);
}

__global__ void __launch_bounds__(256, 6)
tmo_apply(const float* __restrict__ img, float* __restrict__ out) {
    __shared__ uint32_t sBins[GBINS];   // 32 KB
    __shared__ float    sHi[NSEG];      // 1 KB
    __shared__ float2   sAB[NSEG];      // 2 KB

    const int b = blockIdx.y;

    {
        const uint4* src = reinterpret_cast<const uint4*>(gBinsU + (size_t)b * GBINS);
        uint4* dst = reinterpret_cast<uint4*>(sBins);
        for (int i = threadIdx.x; i < GBINS / 4; i += blockDim.x) dst[i] = src[i];
        for (int i = threadIdx.x; i < NSEG; i += blockDim.x) {
            sHi[i] = gSegHi[b * NSEG + i];
            sAB[i] = gSegAB[b * NSEG + i];
        }
    }
    __syncthreads();

    const float4* in4  = reinterpret_cast<const float4*>(img + (size_t)b * PIX_PER_BATCH);
    float4*       out4 = reinterpret_cast<float4*>(out + (size_t)b * PIX_PER_BATCH);

    int i = blockIdx.x * blockDim.x + threadIdx.x;

    #pragma unroll 1
    for (int it = 0; it < PAIRS; it++) {
        float4 va = in4[i];
        float4 vb = in4[i + STRIDE];
        float4 ra, rb;
        ra.x = tmo_eval(va.x, sBins, sHi, sAB);
        rb.x = tmo_eval(vb.x, sBins, sHi, sAB);
        ra.y = tmo_eval(va.y, sBins, sHi, sAB);
        rb.y = tmo_eval(vb.y, sBins, sHi, sAB);
        ra.z = tmo_eval(va.z, sBins, sHi, sAB);
        rb.z = tmo_eval(vb.z, sBins, sHi, sAB);
        ra.w = tmo_eval(va.w, sBins, sHi, sAB);
        rb.w = tmo_eval(vb.w, sBins, sHi, sAB);
        out4[i] = ra;
        out4[i + STRIDE] = rb;
        i += 2 * STRIDE;
    }
    // tail: first 20,736 linear thread ids do one more element
    if (i < NF4) {
        float4 v = in4[i];
        float4 r;
        r.x = tmo_eval(v.x, sBins, sHi, sAB);
        r.y = tmo_eval(v.y, sBins, sHi, sAB);
        r.z = tmo_eval(v.z, sBins, sHi, sAB);
        r.w = tmo_eval(v.w, sBins, sHi, sAB);
        out4[i] = r;
    }
}

extern "C" void kernel_launch(void* const* d_in, const int* in_sizes, int n_in,
                              void* d_out, int out_size) {
    const float* hdr = (const float*)d_in[0];   // [B,C,H,W]
    const float* w   = (const float*)d_in[1];   // [B,NB]
    const float* E   = (const float*)d_in[2];   // [K]
    const float* f0  = (const float*)d_in[3];   // [K]
    const float* Hb  = (const float*)d_in[4];   // [K,NB]
    float* out = (float*)d_out;

    tmo_tables<<<dim3(BB, 33), 256>>>(w, E, f0, Hb);

    dim3 grid(GX, BB);   // 888 blocks = single wave at 6 CTAs/SM
    tmo_apply<<<grid, 256>>>(hdr, out);
}

// round 9
// speedup vs baseline: 1.1217x; 1.1217x over previous
#include <cuda_runtime.h>
#include <cuda_fp16.h>
#include <cfloat>
#include <cstdint>

#define BB 8
#define CC 3
#define HH 1080
#define WW 1920
#define KK 256
#define NBASIS 25
#define GBINS 4096          // power of two: x*4096.0f and frac are EXACT in fp32
#define NSEG (KK + 1)       // 257 extended segments
#define PIX_PER_BATCH (CC * HH * WW)   // 6,220,800
#define NF4 (PIX_PER_BATCH / 4)        // 1,555,200
#define GX 129                          // blocks per batch: 129*8 = 1032 <= 148*7
#define STRIDE (GX * 256)               // 33,024

// Bin entry (uint32):
//   pure bin -> lo16 = half(y_left), hi16 = half(y_right)
//   kinked   -> lo16 = fp16 NaN with payload: 0x7C00 | (k0+1), hi16 = 0x7C00
__device__ uint32_t gBinsU[BB * GBINS];
__device__ float    gSegHi[BB * NSEG];   // segment upper bound E[k] (FLT_MAX for k=K)
__device__ float2   gSegAB[BB * NSEG];   // exact (slope, intercept)

// ---------------------------------------------------------------------------
// Table builder: grid (BB, 17), 256 threads.
//   blockIdx.y in [0,16): build 256 bins each;  ==16: build segment table.
// ---------------------------------------------------------------------------
__global__ void tmo_tables(const float* __restrict__ w,
                           const float* __restrict__ E,
                           const float* __restrict__ f0,
                           const float* __restrict__ Hb) {
    __shared__ float sE[KK];
    __shared__ float sC[KK];
    const int b = blockIdx.x;
    const int part = blockIdx.y;
    const int t = threadIdx.x;

    {
        float acc = f0[t];
        #pragma unroll
        for (int n = 0; n < NBASIS; n++)
            acc = fmaf(Hb[t * NBASIS + n], w[b * NBASIS + n], acc);
        sE[t] = E[t];
        sC[t] = acc;
    }
    __syncthreads();

    if (part == 16) {
        for (int k = t; k < NSEG; k += blockDim.x) {
            float hi; float2 ab;
            if (k == 0) {
                hi = sE[0];            ab = make_float2(0.0f, sC[0]);
            } else if (k == KK) {
                hi = FLT_MAX;          ab = make_float2(0.0f, sC[KK - 1]);
            } else {
                float a = (sC[k] - sC[k - 1]) / (sE[k] - sE[k - 1]);
                hi = sE[k];            ab = make_float2(a, fmaf(-a, sE[k - 1], sC[k - 1]));
            }
            gSegHi[b * NSEG + k] = hi;
            gSegAB[b * NSEG + k] = ab;
        }
    } else {
        const int g = part * 256 + t;
        float left  = (float)g       * (1.0f / GBINS);  // exact
        float right = (float)(g + 1) * (1.0f / GBINS);  // exact
        int lo = 0, hi = KK;
        while (lo < hi) {                // k0 = #E <= left
            int mid = (lo + hi) >> 1;
            if (sE[mid] <= left) lo = mid + 1; else hi = mid;
        }
        int k0 = lo;
        float upper = (k0 < KK) ? sE[k0] : FLT_MAX;
        uint32_t u;
        if (upper >= right) {
            float yl, yr;
            if (k0 == 0) {
                yl = yr = sC[0];
            } else if (k0 == KK) {
                yl = yr = sC[KK - 1];
            } else {
                float a = (sC[k0] - sC[k0 - 1]) / (sE[k0] - sE[k0 - 1]);
                float bint = fmaf(-a, sE[k0 - 1], sC[k0 - 1]);
                yl = fmaf(a, left,  bint);
                yr = fmaf(a, right, bint);
            }
            uint16_t hl = __half_as_ushort(__float2half_rn(yl));
            uint16_t hr = __half_as_ushort(__float2half_rn(yr));
            u = ((uint32_t)hr << 16) | hl;          // finite halfs: never NaN-pattern
        } else {
            u = 0x7C000000u | (0x7C00u | (uint32_t)(k0 + 1));  // NaN sentinel + payload
        }
        gBinsU[b * GBINS + g] = u;
    }
}

// ---------------------------------------------------------------------------
// Fast path: LDS.32 + half2 lerp; NaN result (~6% of lanes) triggers exact
// fp32 segment walk in shared memory.
// ---------------------------------------------------------------------------
__device__ __forceinline__ float tmo_eval(float x, const uint32_t* sBins,
                                          const float* sHi, const float2* sAB) {
    float xg = x * (float)GBINS;           // exact
    int g = (int)xg;                        // x in [0,1) -> g in [0, GBINS-1]
    uint32_t u = sBins[g];
    float2 yy = __half22float2(*reinterpret_cast<const __half2*>(&u));
    float frac = xg - (float)g;            // exact
    float y = fmaf(yy.y - yy.x, frac, yy.x);
    if (!(y == y)) {                        // NaN => kinked bin
        int k = (int)(u & 0x3FFu) - 1;
        while (x >= sHi[k]) k++;
        float2 ab = sAB[k];
        y = fmaf(ab.x, x, ab.y);
    }
    return __saturatef(y);
}

// ---------------------------------------------------------------------------
// Main kernel: grid (129, 8) = 1032 blocks, 7 CTAs/SM (19.6 KB smem, 36-reg
// cap). Software pipeline: next LDG.128 issued before processing current.
// ---------------------------------------------------------------------------
__global__ void __launch_bounds__(256, 7)
tmo_apply(const float* __restrict__ img, float* __restrict__ out) {
    __shared__ uint32_t sBins[GBINS];   // 16 KB
    __shared__ float    sHi[NSEG];      // ~1 KB
    __shared__ float2   sAB[NSEG];      // ~2 KB

    const int b = blockIdx.y;

    {
        const uint4* src = reinterpret_cast<const uint4*>(gBinsU + (size_t)b * GBINS);
        uint4* dst = reinterpret_cast<uint4*>(sBins);
        for (int i = threadIdx.x; i < GBINS / 4; i += blockDim.x) dst[i] = src[i];
        for (int i = threadIdx.x; i < NSEG; i += blockDim.x) {
            sHi[i] = gSegHi[b * NSEG + i];
            sAB[i] = gSegAB[b * NSEG + i];
        }
    }
    __syncthreads();

    const float4* in4  = reinterpret_cast<const float4*>(img + (size_t)b * PIX_PER_BATCH);
    float4*       out4 = reinterpret_cast<float4*>(out + (size_t)b * PIX_PER_BATCH);

    int i = blockIdx.x * blockDim.x + threadIdx.x;   // < STRIDE <= NF4, so >=1 elem

    float4 v = in4[i];
    int nxt = i + STRIDE;

    #pragma unroll 1
    while (nxt < NF4) {
        float4 vn = in4[nxt];            // prefetch: overlaps with processing below
        float4 r;
        r.x = tmo_eval(v.x, sBins, sHi, sAB);
        r.y = tmo_eval(v.y, sBins, sHi, sAB);
        r.z = tmo_eval(v.z, sBins, sHi, sAB);
        r.w = tmo_eval(v.w, sBins, sHi, sAB);
        out4[i] = r;
        v = vn;
        i = nxt;
        nxt += STRIDE;
    }
    {
        float4 r;
        r.x = tmo_eval(v.x, sBins, sHi, sAB);
        r.y = tmo_eval(v.y, sBins, sHi, sAB);
        r.z = tmo_eval(v.z, sBins, sHi, sAB);
        r.w = tmo_eval(v.w, sBins, sHi, sAB);
        out4[i] = r;
    }
}

extern "C" void kernel_launch(void* const* d_in, const int* in_sizes, int n_in,
                              void* d_out, int out_size) {
    const float* hdr = (const float*)d_in[0];   // [B,C,H,W]
    const float* w   = (const float*)d_in[1];   // [B,NB]
    const float* E   = (const float*)d_in[2];   // [K]
    const float* f0  = (const float*)d_in[3];   // [K]
    const float* Hb  = (const float*)d_in[4];   // [K,NB]
    float* out = (float*)d_out;

    tmo_tables<<<dim3(BB, 17), 256>>>(w, E, f0, Hb);

    dim3 grid(GX, BB);   // 1032 blocks = single wave at 7 CTAs/SM
    tmo_apply<<<grid, 256>>>(hdr, out);
}

// round 11
// speedup vs baseline: 1.1473x; 1.0228x over previous
#include <cuda_runtime.h>
#include <cuda_fp16.h>
#include <cfloat>
#include <cstdint>

#define BB 8
#define CC 3
#define HH 1080
#define WW 1920
#define KK 256
#define NBASIS 25
#define GBINS 4096              // bins centered at g/4096, width 1/4096
#define GBINS_PAD 4100          // 4097 used, padded to uint4 multiple
#define NSEG (KK + 1)           // 257 extended segments
#define PIX_PER_BATCH (CC * HH * WW)   // 6,220,800
#define NF4 (PIX_PER_BATCH / 4)        // 1,555,200
#define GX 148                          // blocks per batch: 148*8 = 1184 CTAs
#define STRIDE (GX * 256)               // 37,888
#define MAGIC 8388608.0f                // 2^23

// Bin entry (uint32), bin g covers [(2g-1)/8192, (2g+1)/8192):
//   pure bin -> lo16 = half(y at center g/4096), hi16 = half(dy across bin)
//   kinked   -> lo16 = fp16 NaN with payload 0x7C00|(k0+1), hi16 = 0x7C00
__device__ uint32_t gBinsU[BB * GBINS_PAD];
__device__ float    gSegHi[BB * NSEG];   // segment upper bound E[k] (FLT_MAX for k=K)
__device__ float2   gSegAB[BB * NSEG];   // exact (slope, intercept)

// ---------------------------------------------------------------------------
// Table builder: grid (BB, 17), 256 threads.
//   parts 0..16 build bins g = part*256+t (g <= 4096); part 16 also builds
//   the segment table and zero-pads entries 4097..4099.
// ---------------------------------------------------------------------------
__global__ void tmo_tables(const float* __restrict__ w,
                           const float* __restrict__ E,
                           const float* __restrict__ f0,
                           const float* __restrict__ Hb) {
    __shared__ float sE[KK];
    __shared__ float sC[KK];
    const int b = blockIdx.x;
    const int part = blockIdx.y;
    const int t = threadIdx.x;

    {
        float acc = f0[t];
        #pragma unroll
        for (int n = 0; n < NBASIS; n++)
            acc = fmaf(Hb[t * NBASIS + n], w[b * NBASIS + n], acc);
        sE[t] = E[t];
        sC[t] = acc;
    }
    __syncthreads();

    if (part == 16) {
        for (int k = t; k < NSEG; k += blockDim.x) {
            float hi; float2 ab;
            if (k == 0) {
                hi = sE[0];            ab = make_float2(0.0f, sC[0]);
            } else if (k == KK) {
                hi = FLT_MAX;          ab = make_float2(0.0f, sC[KK - 1]);
            } else {
                float a = (sC[k] - sC[k - 1]) / (sE[k] - sE[k - 1]);
                hi = sE[k];            ab = make_float2(a, fmaf(-a, sE[k - 1], sC[k - 1]));
            }
            gSegHi[b * NSEG + k] = hi;
            gSegAB[b * NSEG + k] = ab;
        }
    }

    const int g = part * 256 + t;
    if (g <= GBINS) {
        float left  = (float)(2 * g - 1) * (1.0f / 8192.0f);  // exact (odd * 2^-13)
        float right = (float)(2 * g + 1) * (1.0f / 8192.0f);  // exact
        int lo = 0, hi = KK;
        while (lo < hi) {                // k0 = #E <= left
            int mid = (lo + hi) >> 1;
            if (sE[mid] <= left) lo = mid + 1; else hi = mid;
        }
        int k0 = lo;
        float upper = (k0 < KK) ? sE[k0] : FLT_MAX;
        uint32_t u;
        if (upper >= right) {
            // entire bin inside extended segment k0: center value + per-bin delta
            float yc, dy;
            if (k0 == 0) {
                yc = sC[0];            dy = 0.0f;
            } else if (k0 == KK) {
                yc = sC[KK - 1];       dy = 0.0f;
            } else {
                float a = (sC[k0] - sC[k0 - 1]) / (sE[k0] - sE[k0 - 1]);
                float bint = fmaf(-a, sE[k0 - 1], sC[k0 - 1]);
                float xc = (float)g * (1.0f / 4096.0f);        // exact
                yc = fmaf(a, xc, bint);
                dy = a * (1.0f / 4096.0f);
            }
            uint16_t hc = __half_as_ushort(__float2half_rn(yc));
            uint16_t hd = __half_as_ushort(__float2half_rn(dy));
            u = ((uint32_t)hd << 16) | hc;          // finite halfs: never NaN-pattern
        } else {
            u = 0x7C000000u | (0x7C00u | (uint32_t)(k0 + 1));  // NaN sentinel + payload
        }
        gBinsU[b * GBINS_PAD + g] = u;
    } else if (part == 16 && g < GBINS_PAD) {
        gBinsU[b * GBINS_PAD + g] = 0;   // padding
    }
}

// ---------------------------------------------------------------------------
// Fast path: magic-number bin index (no CVT ops), LDS.32, center+delta lerp;
// NaN result (~6% of lanes) triggers exact fp32 segment walk in shared.
// ---------------------------------------------------------------------------
__device__ __forceinline__ float tmo_eval(float x, const uint32_t* sBins,
                                          const float* sHi, const float2* sAB) {
    float s = fmaf(x, 4096.0f, MAGIC);          // RN -> integer g in mantissa
    int g = __float_as_int(s) & 0x1FFF;         // g in [0, 4096]
    float gf = s - MAGIC;                       // exact (Sterbenz)
    float frac = fmaf(x, 4096.0f, -gf);         // exact, in [-0.5, 0.5]
    uint32_t u = sBins[g];
    float yc = __half2float(__ushort_as_half((uint16_t)(u & 0xFFFFu)));
    float dy = __half2float(__ushort_as_half((uint16_t)(u >> 16)));
    float y = fmaf(dy, frac, yc);
    if (!(y == y)) {                            // NaN => kinked bin
        int k = (int)(u & 0x3FFu) - 1;
        while (x >= sHi[k]) k++;
        float2 ab = sAB[k];
        y = fmaf(ab.x, x, ab.y);
    }
    return __saturatef(y);
}

// ---------------------------------------------------------------------------
// Main kernel: grid (148, 8) = 1184 blocks = one uniform wave at 8 CTAs/SM
// (19.5 KB smem, 32-reg cap). Software pipeline: next LDG.128 in flight.
// ---------------------------------------------------------------------------
__global__ void __launch_bounds__(256, 8)
tmo_apply(const float* __restrict__ img, float* __restrict__ out) {
    __shared__ uint32_t sBins[GBINS_PAD];   // 16.0 KB
    __shared__ float    sHi[NSEG];          // ~1 KB
    __shared__ float2   sAB[NSEG];          // ~2 KB

    const int b = blockIdx.y;

    {
        const uint4* src = reinterpret_cast<const uint4*>(gBinsU + (size_t)b * GBINS_PAD);
        uint4* dst = reinterpret_cast<uint4*>(sBins);
        for (int i = threadIdx.x; i < GBINS_PAD / 4; i += blockDim.x) dst[i] = src[i];
        for (int i = threadIdx.x; i < NSEG; i += blockDim.x) {
            sHi[i] = gSegHi[b * NSEG + i];
            sAB[i] = gSegAB[b * NSEG + i];
        }
    }
    __syncthreads();

    const float4* in4  = reinterpret_cast<const float4*>(img + (size_t)b * PIX_PER_BATCH);
    float4*       out4 = reinterpret_cast<float4*>(out + (size_t)b * PIX_PER_BATCH);

    int i = blockIdx.x * blockDim.x + threadIdx.x;   // < STRIDE <= NF4, so >=1 elem

    float4 v = in4[i];
    int nxt = i + STRIDE;

    #pragma unroll 1
    while (nxt < NF4) {
        float4 vn = in4[nxt];            // prefetch: overlaps with processing below
        float4 r;
        r.x = tmo_eval(v.x, sBins, sHi, sAB);
        r.y = tmo_eval(v.y, sBins, sHi, sAB);
        r.z = tmo_eval(v.z, sBins, sHi, sAB);
        r.w = tmo_eval(v.w, sBins, sHi, sAB);
        out4[i] = r;
        v = vn;
        i = nxt;
        nxt += STRIDE;
    }
    {
        float4 r;
        r.x = tmo_eval(v.x, sBins, sHi, sAB);
        r.y = tmo_eval(v.y, sBins, sHi, sAB);
        r.z = tmo_eval(v.z, sBins, sHi, sAB);
        r.w = tmo_eval(v.w, sBins, sHi, sAB);
        out4[i] = r;
    }
}

extern "C" void kernel_launch(void* const* d_in, const int* in_sizes, int n_in,
                              void* d_out, int out_size) {
    const float* hdr = (const float*)d_in[0];   // [B,C,H,W]
    const float* w   = (const float*)d_in[1];   // [B,NB]
    const float* E   = (const float*)d_in[2];   // [K]
    const float* f0  = (const float*)d_in[3];   // [K]
    const float* Hb  = (const float*)d_in[4];   // [K,NB]
    float* out = (float*)d_out;

    tmo_tables<<<dim3(BB, 17), 256>>>(w, E, f0, Hb);

    dim3 grid(GX, BB);   // 1184 blocks = single uniform wave at 8 CTAs/SM
    tmo_apply<<<grid, 256>>>(hdr, out);
}